// round 3
// baseline (speedup 1.0000x reference)
#include <cuda_runtime.h>
#include <math.h>

#define NL   4
#define TT   1024
#define NB   4
#define ND   1024
#define NH   16
#define HD   64
#define NFF  4096
#define NM   (TT*NB)      // 4096 rows
#define EPSN 1e-6f

// ---------------- scratch (device globals; no allocations allowed) ----------------
__device__ float g_x[NM * ND];        // layer input (l>=1)
__device__ float g_h[NM * NFF];       // FF hidden
__device__ float g_z[NM * ND];        // after first resnorm
__device__ float g_q[NM * ND];
__device__ float g_k[NM * ND];
__device__ float g_v[NM * ND];
__device__ float g_o[NM * ND];        // ff-out, later attn-out
__device__ float g_s[67108864];       // (NB*NH, TT, TT) attention scores = 256 MB

// ---------------- generic fp32 GEMM: C = act(A[M,K] @ B[K,N] + bias[N]) ----------------
// 128x128 block tile, BK=8, 256 threads, 8x8 per-thread microtile.
template<bool RELU>
__global__ __launch_bounds__(256) void gemm_bias_kernel(
    const float* __restrict__ A, const float* __restrict__ B,
    const float* __restrict__ bias, float* __restrict__ C,
    int M, int N, int K)
{
    __shared__ float As[8][128];
    __shared__ float Bs[8][128];
    const int tid  = threadIdx.x;
    const int trow = tid >> 4;        // 0..15
    const int tcol = tid & 15;        // 0..15
    const int rowA = tid >> 1;        // 0..127
    const int colA = (tid & 1) << 2;  // 0 or 4
    const int rowB = tid >> 5;        // 0..7
    const int colB = (tid & 31) << 2; // 0..124

    const float* Ap = A + (size_t)blockIdx.y * 128 * K;
    const float* Bp = B + (size_t)blockIdx.x * 128;

    float acc[8][8] = {};

    for (int k0 = 0; k0 < K; k0 += 8) {
        float4 a4 = *(const float4*)(Ap + (size_t)rowA * K + k0 + colA);
        As[colA + 0][rowA] = a4.x;
        As[colA + 1][rowA] = a4.y;
        As[colA + 2][rowA] = a4.z;
        As[colA + 3][rowA] = a4.w;
        float4 b4 = *(const float4*)(Bp + (size_t)(k0 + rowB) * N + colB);
        *(float4*)&Bs[rowB][colB] = b4;
        __syncthreads();
        #pragma unroll
        for (int kk = 0; kk < 8; kk++) {
            float ar[8], br[8];
            *(float4*)&ar[0] = *(const float4*)&As[kk][trow * 8];
            *(float4*)&ar[4] = *(const float4*)&As[kk][trow * 8 + 4];
            *(float4*)&br[0] = *(const float4*)&Bs[kk][tcol * 8];
            *(float4*)&br[4] = *(const float4*)&Bs[kk][tcol * 8 + 4];
            #pragma unroll
            for (int i = 0; i < 8; i++)
                #pragma unroll
                for (int j = 0; j < 8; j++)
                    acc[i][j] = fmaf(ar[i], br[j], acc[i][j]);
        }
        __syncthreads();
    }

    float bv[8];
    *(float4*)&bv[0] = *(const float4*)(bias + blockIdx.x * 128 + tcol * 8);
    *(float4*)&bv[4] = *(const float4*)(bias + blockIdx.x * 128 + tcol * 8 + 4);

    float* Cp = C + ((size_t)blockIdx.y * 128 + trow * 8) * N + blockIdx.x * 128 + tcol * 8;
    #pragma unroll
    for (int i = 0; i < 8; i++) {
        float4 o0, o1;
        o0.x = acc[i][0] + bv[0]; o0.y = acc[i][1] + bv[1];
        o0.z = acc[i][2] + bv[2]; o0.w = acc[i][3] + bv[3];
        o1.x = acc[i][4] + bv[4]; o1.y = acc[i][5] + bv[5];
        o1.z = acc[i][6] + bv[6]; o1.w = acc[i][7] + bv[7];
        if (RELU) {
            o0.x = fmaxf(o0.x, 0.f); o0.y = fmaxf(o0.y, 0.f);
            o0.z = fmaxf(o0.z, 0.f); o0.w = fmaxf(o0.w, 0.f);
            o1.x = fmaxf(o1.x, 0.f); o1.y = fmaxf(o1.y, 0.f);
            o1.z = fmaxf(o1.z, 0.f); o1.w = fmaxf(o1.w, 0.f);
        }
        *(float4*)(Cp + (size_t)i * N)     = o0;
        *(float4*)(Cp + (size_t)i * N + 4) = o1;
    }
}

// ---------------- resnorm: out = ((x+fx) - mean) / (std_ddof1 + eps), per row of ND ----------------
__global__ __launch_bounds__(256) void resnorm_kernel(
    const float* __restrict__ x, const float* __restrict__ fx, float* __restrict__ out)
{
    const int row = blockIdx.x;
    const int tid = threadIdx.x;
    const int lane = tid & 31, warp = tid >> 5;
    __shared__ float red0[8], red1[8], stat[2];

    const float* xp = x + (size_t)row * ND + tid * 4;
    const float* fp = fx + (size_t)row * ND + tid * 4;
    float4 xv = *(const float4*)xp;
    float4 fv = *(const float4*)fp;
    float4 y;
    y.x = xv.x + fv.x; y.y = xv.y + fv.y; y.z = xv.z + fv.z; y.w = xv.w + fv.w;

    float s  = y.x + y.y + y.z + y.w;
    float s2 = y.x * y.x + y.y * y.y + y.z * y.z + y.w * y.w;
    #pragma unroll
    for (int o = 16; o > 0; o >>= 1) {
        s  += __shfl_xor_sync(0xffffffffu, s, o);
        s2 += __shfl_xor_sync(0xffffffffu, s2, o);
    }
    if (lane == 0) { red0[warp] = s; red1[warp] = s2; }
    __syncthreads();
    if (tid == 0) {
        float a = 0.f, b = 0.f;
        #pragma unroll
        for (int w = 0; w < 8; w++) { a += red0[w]; b += red1[w]; }
        float mu  = a / (float)ND;
        float var = (b - a * mu) / (float)(ND - 1);
        stat[0] = mu;
        stat[1] = 1.f / (sqrtf(fmaxf(var, 0.f)) + EPSN);
    }
    __syncthreads();
    const float mu = stat[0], inv = stat[1];
    float4 o;
    o.x = (y.x - mu) * inv; o.y = (y.y - mu) * inv;
    o.z = (y.z - mu) * inv; o.w = (y.w - mu) * inv;
    *(float4*)(out + (size_t)row * ND + tid * 4) = o;
}

// ---------------- attention scores: S[bh,i,j] = dot(K_i, Q_j) / sqrt(D) ----------------
// one block = 64x64 tile of S for one (b,h). K dims = 64 (full DQK).
__global__ __launch_bounds__(256) void attn_scores_kernel(
    const float* __restrict__ Kb, const float* __restrict__ Qb, float* __restrict__ S)
{
    const int bh = blockIdx.z;
    const int b = bh / NH, h = bh % NH;
    const int i0 = blockIdx.y * 64;
    const int j0 = blockIdx.x * 64;
    __shared__ float Ks[HD][65];   // Ks[d][i]
    __shared__ float Qs[HD][65];   // Qs[d][j]
    const int tid = threadIdx.x;

    #pragma unroll
    for (int t = 0; t < 4; t++) {
        int idx = tid + t * 256;
        int r = idx >> 4;
        int c = (idx & 15) << 2;
        float4 kv = *(const float4*)(Kb + ((size_t)(i0 + r) * NB + b) * ND + h * HD + c);
        Ks[c + 0][r] = kv.x; Ks[c + 1][r] = kv.y; Ks[c + 2][r] = kv.z; Ks[c + 3][r] = kv.w;
        float4 qv = *(const float4*)(Qb + ((size_t)(j0 + r) * NB + b) * ND + h * HD + c);
        Qs[c + 0][r] = qv.x; Qs[c + 1][r] = qv.y; Qs[c + 2][r] = qv.z; Qs[c + 3][r] = qv.w;
    }
    __syncthreads();

    const int tcol = tid & 15, trow = tid >> 4;
    float acc[4][4] = {};
    #pragma unroll
    for (int d = 0; d < HD; d++) {
        float kr[4], qr[4];
        #pragma unroll
        for (int i = 0; i < 4; i++) kr[i] = Ks[d][trow * 4 + i];
        #pragma unroll
        for (int j = 0; j < 4; j++) qr[j] = Qs[d][tcol * 4 + j];
        #pragma unroll
        for (int i = 0; i < 4; i++)
            #pragma unroll
            for (int j = 0; j < 4; j++)
                acc[i][j] = fmaf(kr[i], qr[j], acc[i][j]);
    }

    float* Sp = S + ((size_t)bh * TT + i0) * TT + j0;
    #pragma unroll
    for (int i = 0; i < 4; i++) {
        float4 o;
        o.x = acc[i][0] * 0.03125f; o.y = acc[i][1] * 0.03125f;
        o.z = acc[i][2] * 0.03125f; o.w = acc[i][3] * 0.03125f;
        *(float4*)(Sp + (size_t)(trow * 4 + i) * TT + tcol * 4) = o;
    }
}

// ---------------- row softmax over last axis (mask is all-true) ----------------
__global__ __launch_bounds__(256) void softmax_kernel(float* __restrict__ S)
{
    float* p = S + (size_t)blockIdx.x * TT;
    const int tid = threadIdx.x;
    const int lane = tid & 31, warp = tid >> 5;
    __shared__ float red[8], bc[1];

    float4 v = *(float4*)(p + tid * 4);
    float m = fmaxf(fmaxf(v.x, v.y), fmaxf(v.z, v.w));
    #pragma unroll
    for (int o = 16; o > 0; o >>= 1) m = fmaxf(m, __shfl_xor_sync(0xffffffffu, m, o));
    if (lane == 0) red[warp] = m;
    __syncthreads();
    float bm = red[0];
    #pragma unroll
    for (int w = 1; w < 8; w++) bm = fmaxf(bm, red[w]);

    v.x = __expf(v.x - bm); v.y = __expf(v.y - bm);
    v.z = __expf(v.z - bm); v.w = __expf(v.w - bm);
    float s = v.x + v.y + v.z + v.w;
    #pragma unroll
    for (int o = 16; o > 0; o >>= 1) s += __shfl_xor_sync(0xffffffffu, s, o);
    __syncthreads();
    if (lane == 0) red[warp] = s;
    __syncthreads();
    if (tid == 0) {
        float a = 0.f;
        #pragma unroll
        for (int w = 0; w < 8; w++) a += red[w];
        bc[0] = 1.f / a;
    }
    __syncthreads();
    const float inv = bc[0];
    v.x *= inv; v.y *= inv; v.z *= inv; v.w *= inv;
    *(float4*)(p + tid * 4) = v;
}

// ---------------- attention output: O[i, :] = sum_j A[i,j] * V[j, :] per (b,h) ----------------
// one block = 64 i-rows x 64 dv-cols (full DV), loop over j in chunks of 64.
__global__ __launch_bounds__(256) void attn_out_kernel(
    const float* __restrict__ S, const float* __restrict__ Vb, float* __restrict__ O)
{
    const int bh = blockIdx.y;
    const int b = bh / NH, h = bh % NH;
    const int i0 = blockIdx.x * 64;
    __shared__ float As[64][65];   // As[j_local][i_local]
    __shared__ float Vs[64][68];   // Vs[j_local][dv]
    const int tid = threadIdx.x;
    const int tcol = tid & 15, trow = tid >> 4;
    const float* Sp = S + ((size_t)bh * TT + i0) * TT;

    float acc[4][4] = {};
    for (int j0 = 0; j0 < TT; j0 += 64) {
        #pragma unroll
        for (int t = 0; t < 4; t++) {
            int idx = tid + t * 256;
            int r = idx >> 4;
            int c = (idx & 15) << 2;
            float4 a4 = *(const float4*)(Sp + (size_t)r * TT + j0 + c);
            As[c + 0][r] = a4.x; As[c + 1][r] = a4.y; As[c + 2][r] = a4.z; As[c + 3][r] = a4.w;
            float4 v4 = *(const float4*)(Vb + ((size_t)(j0 + r) * NB + b) * ND + h * HD + c);
            *(float4*)&Vs[r][c] = v4;
        }
        __syncthreads();
        #pragma unroll
        for (int kk = 0; kk < 64; kk++) {
            float ar[4], vr[4];
            #pragma unroll
            for (int i = 0; i < 4; i++) ar[i] = As[kk][trow * 4 + i];
            #pragma unroll
            for (int j = 0; j < 4; j++) vr[j] = Vs[kk][tcol * 4 + j];
            #pragma unroll
            for (int i = 0; i < 4; i++)
                #pragma unroll
                for (int j = 0; j < 4; j++)
                    acc[i][j] = fmaf(ar[i], vr[j], acc[i][j]);
        }
        __syncthreads();
    }

    #pragma unroll
    for (int i = 0; i < 4; i++) {
        float4 o;
        o.x = acc[i][0]; o.y = acc[i][1]; o.z = acc[i][2]; o.w = acc[i][3];
        *(float4*)(O + ((size_t)(i0 + trow * 4 + i) * NB + b) * ND + h * HD + tcol * 4) = o;
    }
}

// ---------------- host launcher ----------------
extern "C" void kernel_launch(void* const* d_in, const int* in_sizes, int n_in,
                              void* d_out, int out_size)
{
    const float* x_in = (const float*)d_in[0];
    // d_in[1] = mask (all true in this problem; softmax unmasked)
    const float* Wk = (const float*)d_in[2];
    const float* bk = (const float*)d_in[3];
    const float* Wq = (const float*)d_in[4];
    const float* bq = (const float*)d_in[5];
    const float* Wv = (const float*)d_in[6];
    const float* bv = (const float*)d_in[7];
    const float* W1 = (const float*)d_in[8];
    const float* b1 = (const float*)d_in[9];
    const float* W2 = (const float*)d_in[10];
    const float* b2 = (const float*)d_in[11];
    float* out = (float*)d_out;

    void *px, *ph, *pz, *pq, *pk, *pv, *po, *ps;
    cudaGetSymbolAddress(&px, g_x);
    cudaGetSymbolAddress(&ph, g_h);
    cudaGetSymbolAddress(&pz, g_z);
    cudaGetSymbolAddress(&pq, g_q);
    cudaGetSymbolAddress(&pk, g_k);
    cudaGetSymbolAddress(&pv, g_v);
    cudaGetSymbolAddress(&po, g_o);
    cudaGetSymbolAddress(&ps, g_s);
    float* gx = (float*)px; float* gh = (float*)ph; float* gz = (float*)pz;
    float* gq = (float*)pq; float* gk = (float*)pk; float* gv = (float*)pv;
    float* go = (float*)po; float* gs = (float*)ps;

    const float* cur = x_in;
    for (int l = 0; l < NL; l++) {
        // FF: h = relu(x @ W1 + b1); f = relu(h @ W2 + b2)
        gemm_bias_kernel<true><<<dim3(NFF / 128, NM / 128), 256>>>(
            cur, W1 + (size_t)l * ND * NFF, b1 + (size_t)l * NFF, gh, NM, NFF, ND);
        gemm_bias_kernel<true><<<dim3(ND / 128, NM / 128), 256>>>(
            gh, W2 + (size_t)l * NFF * ND, b2 + (size_t)l * ND, go, NM, ND, NFF);
        // z = resnorm(x, f)
        resnorm_kernel<<<NM, 256>>>(cur, go, gz);
        // Q, K, V projections
        gemm_bias_kernel<false><<<dim3(ND / 128, NM / 128), 256>>>(
            gz, Wq + (size_t)l * ND * ND, bq + (size_t)l * ND, gq, NM, ND, ND);
        gemm_bias_kernel<false><<<dim3(ND / 128, NM / 128), 256>>>(
            gz, Wk + (size_t)l * ND * ND, bk + (size_t)l * ND, gk, NM, ND, ND);
        gemm_bias_kernel<false><<<dim3(ND / 128, NM / 128), 256>>>(
            gz, Wv + (size_t)l * ND * ND, bv + (size_t)l * ND, gv, NM, ND, ND);
        // S = K Q^T / sqrt(D); softmax over j; O = A V
        attn_scores_kernel<<<dim3(TT / 64, TT / 64, NB * NH), 256>>>(gk, gq, gs);
        softmax_kernel<<<NB * NH * TT, 256>>>(gs);
        attn_out_kernel<<<dim3(TT / 64, NB * NH), 256>>>(gs, gv, go);
        // x = resnorm(z, attn_out)
        float* dst = (l == NL - 1) ? out : gx;
        resnorm_kernel<<<NM, 256>>>(gz, go, dst);
        cur = gx;
    }
}

// round 9
// speedup vs baseline: 2.1414x; 2.1414x over previous
#include <cuda_runtime.h>
#include <math.h>
#include <stdint.h>

#define NL   4
#define TT   1024
#define NB   4
#define ND   1024
#define NH   16
#define HD   64
#define NFF  4096
#define NM   (TT*NB)      // 4096 rows
#define EPSN 1e-6f

// ---------------- scratch (device globals; no allocations allowed) ----------------
__device__ float g_x[NM * ND];
__device__ float g_h[NM * NFF];
__device__ float g_z[NM * ND];
__device__ float g_q[NM * ND];
__device__ float g_k[NM * ND];
__device__ float g_v[NM * ND];
__device__ float g_o[NM * ND];
__device__ float g_s[67108864];       // (NB*NH, TT, TT) scores, 256 MB

// ---------------- bf16 mma + split helpers ----------------
// D += A*B with m16n8k16 bf16, fp32 accumulate.
__device__ __forceinline__ void mma16(float* c, const uint32_t* a, const uint32_t* b) {
    asm volatile(
        "mma.sync.aligned.m16n8k16.row.col.f32.bf16.bf16.f32 "
        "{%0,%1,%2,%3}, {%4,%5,%6,%7}, {%8,%9}, {%0,%1,%2,%3};\n"
        : "+f"(c[0]), "+f"(c[1]), "+f"(c[2]), "+f"(c[3])
        : "r"(a[0]), "r"(a[1]), "r"(a[2]), "r"(a[3]), "r"(b[0]), "r"(b[1]));
}
// Split (x,y) fp32 pair into packed bf16 hi {lo=x,hi=y} and bf16 lo (residuals).
__device__ __forceinline__ void bsplit(float x, float y, uint32_t& hi, uint32_t& lo) {
    uint32_t h;
    asm("cvt.rn.bf16x2.f32 %0, %1, %2;" : "=r"(h) : "f"(y), "f"(x));
    float xr = x - __uint_as_float(h << 16);
    float yr = y - __uint_as_float(h & 0xffff0000u);
    asm("cvt.rn.bf16x2.f32 %0, %1, %2;" : "=r"(lo) : "f"(yr), "f"(xr));
    hi = h;
}
__device__ __forceinline__ void cpa16(float* dst, const float* src) {
    uint32_t d = (uint32_t)__cvta_generic_to_shared(dst);
    asm volatile("cp.async.cg.shared.global [%0], [%1], 16;\n" :: "r"(d), "l"(src));
}
__device__ __forceinline__ void cp_commit() { asm volatile("cp.async.commit_group;\n"); }
template<int N> __device__ __forceinline__ void cp_wait() { asm volatile("cp.async.wait_group %0;\n" :: "n"(N)); }

// ======================= projection/FF GEMM (NN): C = act(A@B + bias) =======================
// 128x128x32 CTA tile, 256 threads, warp grid 2x4 (warp tile 64x32), double-buffered cp.async.
#define ASTR 36
#define BSTR 132

template<bool RELU>
__global__ __launch_bounds__(256) void mma_gemm_nn(
    const float* __restrict__ A, const float* __restrict__ B,
    const float* __restrict__ bias, float* __restrict__ C,
    int M, int N, int K)
{
    extern __shared__ float sm[];
    float* As = sm;                      // [2][128][ASTR]
    float* Bs = sm + 2 * 128 * ASTR;     // [2][32][BSTR]

    const int tid  = threadIdx.x;
    const int warp = tid >> 5, lane = tid & 31;
    const int g = lane >> 2, t = lane & 3;
    const int wm = warp >> 2, wn = warp & 3;
    const int m0 = blockIdx.y * 128, n0 = blockIdx.x * 128;

    const int nk = K >> 5;

    auto load_stage = [&](int s, int k0) {
        float* Ad = As + s * 128 * ASTR;
        float* Bd = Bs + s * 32 * BSTR;
        #pragma unroll
        for (int q = 0; q < 4; q++) {
            int c = tid + 256 * q;
            int r = c >> 3, col = (c & 7) << 2;
            cpa16(Ad + r * ASTR + col, A + (size_t)(m0 + r) * K + k0 + col);
        }
        #pragma unroll
        for (int q = 0; q < 4; q++) {
            int c = tid + 256 * q;
            int r = c >> 5, col = (c & 31) << 2;
            cpa16(Bd + r * BSTR + col, B + (size_t)(k0 + r) * N + n0 + col);
        }
    };

    float acc[4][4][4] = {};

    load_stage(0, 0);
    cp_commit();

    for (int kt = 0; kt < nk; kt++) {
        int s = kt & 1;
        if (kt + 1 < nk) {
            load_stage((kt + 1) & 1, (kt + 1) << 5);
            cp_commit();
            cp_wait<1>();
        } else {
            cp_wait<0>();
        }
        __syncthreads();

        const float* Asl = As + s * 128 * ASTR + wm * 64 * ASTR;
        const float* Bsl = Bs + s * 32 * BSTR + wn * 32;
        #pragma unroll
        for (int kk = 0; kk < 32; kk += 16) {
            // B fragments for all 4 j-tiles (hi/lo)
            uint32_t bhi[4][2], blo[4][2];
            #pragma unroll
            for (int j = 0; j < 4; j++) {
                int n = j * 8 + g;
                float x0 = Bsl[(kk + 2 * t)     * BSTR + n];
                float x1 = Bsl[(kk + 2 * t + 1) * BSTR + n];
                float x2 = Bsl[(kk + 2 * t + 8) * BSTR + n];
                float x3 = Bsl[(kk + 2 * t + 9) * BSTR + n];
                bsplit(x0, x1, bhi[j][0], blo[j][0]);
                bsplit(x2, x3, bhi[j][1], blo[j][1]);
            }
            #pragma unroll
            for (int i = 0; i < 4; i++) {
                const float* p = Asl + (i * 16 + g) * ASTR + kk + 2 * t;
                float2 v00 = *(const float2*)(p);
                float2 v10 = *(const float2*)(p + 8 * ASTR);
                float2 v01 = *(const float2*)(p + 8);
                float2 v11 = *(const float2*)(p + 8 * ASTR + 8);
                uint32_t ahi[4], alo[4];
                bsplit(v00.x, v00.y, ahi[0], alo[0]);
                bsplit(v10.x, v10.y, ahi[1], alo[1]);
                bsplit(v01.x, v01.y, ahi[2], alo[2]);
                bsplit(v11.x, v11.y, ahi[3], alo[3]);
                #pragma unroll
                for (int j = 0; j < 4; j++) {
                    mma16(acc[i][j], ahi, bhi[j]);
                    mma16(acc[i][j], ahi, blo[j]);
                    mma16(acc[i][j], alo, bhi[j]);
                }
            }
        }
        __syncthreads();
    }

    #pragma unroll
    for (int i = 0; i < 4; i++) {
        int row = m0 + wm * 64 + i * 16 + g;
        #pragma unroll
        for (int j = 0; j < 4; j++) {
            int col = n0 + wn * 32 + j * 8 + 2 * t;
            float b0 = bias[col], b1 = bias[col + 1];
            float v0 = acc[i][j][0] + b0, v1 = acc[i][j][1] + b1;
            float v2 = acc[i][j][2] + b0, v3 = acc[i][j][3] + b1;
            if (RELU) {
                v0 = fmaxf(v0, 0.f); v1 = fmaxf(v1, 0.f);
                v2 = fmaxf(v2, 0.f); v3 = fmaxf(v3, 0.f);
            }
            *(float2*)(C + (size_t)row * N + col)       = make_float2(v0, v1);
            *(float2*)(C + (size_t)(row + 8) * N + col) = make_float2(v2, v3);
        }
    }
}

// ======================= attention scores (NT): S[bh,i,j] = K_i . Q_j / 32 =======================
#define SSTR 68
__global__ __launch_bounds__(256) void mma_attn_scores(
    const float* __restrict__ Kb, const float* __restrict__ Qb, float* __restrict__ S)
{
    extern __shared__ float sm[];
    float* Ks = sm;              // [128][SSTR]
    float* Qs = sm + 128 * SSTR; // [128][SSTR]

    const int bh = blockIdx.z, b = bh >> 4, h = bh & 15;
    const int i0 = blockIdx.y * 128, j0 = blockIdx.x * 128;
    const int tid  = threadIdx.x;
    const int warp = tid >> 5, lane = tid & 31;
    const int g = lane >> 2, t = lane & 3;
    const int wm = warp >> 2, wn = warp & 3;

    const size_t base = (size_t)b * ND + (size_t)h * HD;
    #pragma unroll
    for (int q = 0; q < 8; q++) {
        int c = tid + 256 * q;
        int r = c >> 4, col = (c & 15) << 2;
        *(float4*)(Ks + r * SSTR + col) =
            *(const float4*)(Kb + base + (size_t)(i0 + r) * (NB * ND) + col);
        *(float4*)(Qs + r * SSTR + col) =
            *(const float4*)(Qb + base + (size_t)(j0 + r) * (NB * ND) + col);
    }
    __syncthreads();

    float acc[4][4][4] = {};
    const float* Asl = Ks + wm * 64 * SSTR;
    const float* Bsl = Qs + wn * 32 * SSTR;
    #pragma unroll
    for (int kk = 0; kk < 64; kk += 16) {
        uint32_t bhi[4][2], blo[4][2];
        #pragma unroll
        for (int j = 0; j < 4; j++) {
            const float* p = Bsl + (j * 8 + g) * SSTR + kk + 2 * t;
            float2 u0 = *(const float2*)(p);
            float2 u1 = *(const float2*)(p + 8);
            bsplit(u0.x, u0.y, bhi[j][0], blo[j][0]);
            bsplit(u1.x, u1.y, bhi[j][1], blo[j][1]);
        }
        #pragma unroll
        for (int i = 0; i < 4; i++) {
            const float* p = Asl + (i * 16 + g) * SSTR + kk + 2 * t;
            float2 v00 = *(const float2*)(p);
            float2 v10 = *(const float2*)(p + 8 * SSTR);
            float2 v01 = *(const float2*)(p + 8);
            float2 v11 = *(const float2*)(p + 8 * SSTR + 8);
            uint32_t ahi[4], alo[4];
            bsplit(v00.x, v00.y, ahi[0], alo[0]);
            bsplit(v10.x, v10.y, ahi[1], alo[1]);
            bsplit(v01.x, v01.y, ahi[2], alo[2]);
            bsplit(v11.x, v11.y, ahi[3], alo[3]);
            #pragma unroll
            for (int j = 0; j < 4; j++) {
                mma16(acc[i][j], ahi, bhi[j]);
                mma16(acc[i][j], ahi, blo[j]);
                mma16(acc[i][j], alo, bhi[j]);
            }
        }
    }

    float* Sp = S + (size_t)bh * TT * TT;
    #pragma unroll
    for (int i = 0; i < 4; i++) {
        int row = i0 + wm * 64 + i * 16 + g;
        #pragma unroll
        for (int j = 0; j < 4; j++) {
            int col = j0 + wn * 32 + j * 8 + 2 * t;
            *(float2*)(Sp + (size_t)row * TT + col) =
                make_float2(acc[i][j][0] * 0.03125f, acc[i][j][1] * 0.03125f);
            *(float2*)(Sp + (size_t)(row + 8) * TT + col) =
                make_float2(acc[i][j][2] * 0.03125f, acc[i][j][3] * 0.03125f);
        }
    }
}

// ======================= attention output (NN): O = A @ V per head =======================
#define VSTR 68
__global__ __launch_bounds__(256) void mma_attn_out(
    const float* __restrict__ S, const float* __restrict__ Vb, float* __restrict__ O)
{
    extern __shared__ float sm[];
    float* As = sm;                   // [2][128][ASTR]
    float* Bs = sm + 2 * 128 * ASTR;  // [2][32][VSTR]

    const int bh = blockIdx.y, b = bh >> 4, h = bh & 15;
    const int i0 = blockIdx.x * 128;
    const int tid  = threadIdx.x;
    const int warp = tid >> 5, lane = tid & 31;
    const int g = lane >> 2, t = lane & 3;
    const int wm = warp >> 2, wn = warp & 3;

    const float* Sp = S + (size_t)bh * TT * TT + (size_t)i0 * TT;
    const size_t baseV = (size_t)b * ND + (size_t)h * HD;

    auto load_stage = [&](int s, int k0) {
        float* Ad = As + s * 128 * ASTR;
        float* Bd = Bs + s * 32 * VSTR;
        #pragma unroll
        for (int q = 0; q < 4; q++) {
            int c = tid + 256 * q;
            int r = c >> 3, col = (c & 7) << 2;
            cpa16(Ad + r * ASTR + col, Sp + (size_t)r * TT + k0 + col);
        }
        #pragma unroll
        for (int q = 0; q < 2; q++) {
            int c = tid + 256 * q;
            int r = c >> 4, col = (c & 15) << 2;
            cpa16(Bd + r * VSTR + col, Vb + baseV + (size_t)(k0 + r) * (NB * ND) + col);
        }
    };

    float acc[4][2][4] = {};

    load_stage(0, 0);
    cp_commit();

    const int nk = TT >> 5;
    for (int kt = 0; kt < nk; kt++) {
        int s = kt & 1;
        if (kt + 1 < nk) {
            load_stage((kt + 1) & 1, (kt + 1) << 5);
            cp_commit();
            cp_wait<1>();
        } else {
            cp_wait<0>();
        }
        __syncthreads();

        const float* Asl = As + s * 128 * ASTR + wm * 64 * ASTR;
        const float* Bsl = Bs + s * 32 * VSTR + wn * 16;
        #pragma unroll
        for (int kk = 0; kk < 32; kk += 16) {
            uint32_t bhi[2][2], blo[2][2];
            #pragma unroll
            for (int j = 0; j < 2; j++) {
                int n = j * 8 + g;
                float x0 = Bsl[(kk + 2 * t)     * VSTR + n];
                float x1 = Bsl[(kk + 2 * t + 1) * VSTR + n];
                float x2 = Bsl[(kk + 2 * t + 8) * VSTR + n];
                float x3 = Bsl[(kk + 2 * t + 9) * VSTR + n];
                bsplit(x0, x1, bhi[j][0], blo[j][0]);
                bsplit(x2, x3, bhi[j][1], blo[j][1]);
            }
            #pragma unroll
            for (int i = 0; i < 4; i++) {
                const float* p = Asl + (i * 16 + g) * ASTR + kk + 2 * t;
                float2 v00 = *(const float2*)(p);
                float2 v10 = *(const float2*)(p + 8 * ASTR);
                float2 v01 = *(const float2*)(p + 8);
                float2 v11 = *(const float2*)(p + 8 * ASTR + 8);
                uint32_t ahi[4], alo[4];
                bsplit(v00.x, v00.y, ahi[0], alo[0]);
                bsplit(v10.x, v10.y, ahi[1], alo[1]);
                bsplit(v01.x, v01.y, ahi[2], alo[2]);
                bsplit(v11.x, v11.y, ahi[3], alo[3]);
                #pragma unroll
                for (int j = 0; j < 2; j++) {
                    mma16(acc[i][j], ahi, bhi[j]);
                    mma16(acc[i][j], ahi, blo[j]);
                    mma16(acc[i][j], alo, bhi[j]);
                }
            }
        }
        __syncthreads();
    }

    #pragma unroll
    for (int i = 0; i < 4; i++) {
        int row = i0 + wm * 64 + i * 16 + g;
        #pragma unroll
        for (int j = 0; j < 2; j++) {
            int col = wn * 16 + j * 8 + 2 * t;
            *(float2*)(O + ((size_t)row * NB + b) * ND + h * HD + col) =
                make_float2(acc[i][j][0], acc[i][j][1]);
            *(float2*)(O + ((size_t)(row + 8) * NB + b) * ND + h * HD + col) =
                make_float2(acc[i][j][2], acc[i][j][3]);
        }
    }
}

// ---------------- resnorm ----------------
__global__ __launch_bounds__(256) void resnorm_kernel(
    const float* __restrict__ x, const float* __restrict__ fx, float* __restrict__ out)
{
    const int row = blockIdx.x;
    const int tid = threadIdx.x;
    const int lane = tid & 31, warp = tid >> 5;
    __shared__ float red0[8], red1[8], stat[2];

    float4 xv = *(const float4*)(x + (size_t)row * ND + tid * 4);
    float4 fv = *(const float4*)(fx + (size_t)row * ND + tid * 4);
    float4 y;
    y.x = xv.x + fv.x; y.y = xv.y + fv.y; y.z = xv.z + fv.z; y.w = xv.w + fv.w;

    float s  = y.x + y.y + y.z + y.w;
    float s2 = y.x * y.x + y.y * y.y + y.z * y.z + y.w * y.w;
    #pragma unroll
    for (int o = 16; o > 0; o >>= 1) {
        s  += __shfl_xor_sync(0xffffffffu, s, o);
        s2 += __shfl_xor_sync(0xffffffffu, s2, o);
    }
    if (lane == 0) { red0[warp] = s; red1[warp] = s2; }
    __syncthreads();
    if (tid == 0) {
        float a = 0.f, bb = 0.f;
        #pragma unroll
        for (int w = 0; w < 8; w++) { a += red0[w]; bb += red1[w]; }
        float mu  = a / (float)ND;
        float var = (bb - a * mu) / (float)(ND - 1);
        stat[0] = mu;
        stat[1] = 1.f / (sqrtf(fmaxf(var, 0.f)) + EPSN);
    }
    __syncthreads();
    const float mu = stat[0], inv = stat[1];
    float4 o;
    o.x = (y.x - mu) * inv; o.y = (y.y - mu) * inv;
    o.z = (y.z - mu) * inv; o.w = (y.w - mu) * inv;
    *(float4*)(out + (size_t)row * ND + tid * 4) = o;
}

// ---------------- row softmax (mask all-true) ----------------
__global__ __launch_bounds__(256) void softmax_kernel(float* __restrict__ S)
{
    float* p = S + (size_t)blockIdx.x * TT;
    const int tid = threadIdx.x;
    const int lane = tid & 31, warp = tid >> 5;
    __shared__ float red[8], bc[1];

    float4 v = *(float4*)(p + tid * 4);
    float m = fmaxf(fmaxf(v.x, v.y), fmaxf(v.z, v.w));
    #pragma unroll
    for (int o = 16; o > 0; o >>= 1) m = fmaxf(m, __shfl_xor_sync(0xffffffffu, m, o));
    if (lane == 0) red[warp] = m;
    __syncthreads();
    float bm = red[0];
    #pragma unroll
    for (int w = 1; w < 8; w++) bm = fmaxf(bm, red[w]);

    v.x = __expf(v.x - bm); v.y = __expf(v.y - bm);
    v.z = __expf(v.z - bm); v.w = __expf(v.w - bm);
    float s = v.x + v.y + v.z + v.w;
    #pragma unroll
    for (int o = 16; o > 0; o >>= 1) s += __shfl_xor_sync(0xffffffffu, s, o);
    __syncthreads();
    if (lane == 0) red[warp] = s;
    __syncthreads();
    if (tid == 0) {
        float a = 0.f;
        #pragma unroll
        for (int w = 0; w < 8; w++) a += red[w];
        bc[0] = 1.f / a;
    }
    __syncthreads();
    const float inv = bc[0];
    v.x *= inv; v.y *= inv; v.z *= inv; v.w *= inv;
    *(float4*)(p + tid * 4) = v;
}

// ---------------- host launcher ----------------
extern "C" void kernel_launch(void* const* d_in, const int* in_sizes, int n_in,
                              void* d_out, int out_size)
{
    const float* x_in = (const float*)d_in[0];
    const float* Wk = (const float*)d_in[2];
    const float* bk = (const float*)d_in[3];
    const float* Wq = (const float*)d_in[4];
    const float* bq = (const float*)d_in[5];
    const float* Wv = (const float*)d_in[6];
    const float* bv = (const float*)d_in[7];
    const float* W1 = (const float*)d_in[8];
    const float* b1 = (const float*)d_in[9];
    const float* W2 = (const float*)d_in[10];
    const float* b2 = (const float*)d_in[11];
    float* out = (float*)d_out;

    const int SMEM_NN = (2 * 128 * ASTR + 2 * 32 * BSTR) * 4;   // 70656
    const int SMEM_SC = (2 * 128 * SSTR) * 4;                    // 69632
    const int SMEM_AV = (2 * 128 * ASTR + 2 * 32 * VSTR) * 4;    // 54272
    cudaFuncSetAttribute(mma_gemm_nn<true>,  cudaFuncAttributeMaxDynamicSharedMemorySize, SMEM_NN);
    cudaFuncSetAttribute(mma_gemm_nn<false>, cudaFuncAttributeMaxDynamicSharedMemorySize, SMEM_NN);
    cudaFuncSetAttribute(mma_attn_scores,    cudaFuncAttributeMaxDynamicSharedMemorySize, SMEM_SC);
    cudaFuncSetAttribute(mma_attn_out,       cudaFuncAttributeMaxDynamicSharedMemorySize, SMEM_AV);

    void *px, *ph, *pz, *pq, *pk, *pv, *po, *ps;
    cudaGetSymbolAddress(&px, g_x);
    cudaGetSymbolAddress(&ph, g_h);
    cudaGetSymbolAddress(&pz, g_z);
    cudaGetSymbolAddress(&pq, g_q);
    cudaGetSymbolAddress(&pk, g_k);
    cudaGetSymbolAddress(&pv, g_v);
    cudaGetSymbolAddress(&po, g_o);
    cudaGetSymbolAddress(&ps, g_s);
    float* gx = (float*)px; float* gh = (float*)ph; float* gz = (float*)pz;
    float* gq = (float*)pq; float* gk = (float*)pk; float* gv = (float*)pv;
    float* go = (float*)po; float* gs = (float*)ps;

    const float* cur = x_in;
    for (int l = 0; l < NL; l++) {
        mma_gemm_nn<true><<<dim3(NFF / 128, NM / 128), 256, SMEM_NN>>>(
            cur, W1 + (size_t)l * ND * NFF, b1 + (size_t)l * NFF, gh, NM, NFF, ND);
        mma_gemm_nn<true><<<dim3(ND / 128, NM / 128), 256, SMEM_NN>>>(
            gh, W2 + (size_t)l * NFF * ND, b2 + (size_t)l * ND, go, NM, ND, NFF);
        resnorm_kernel<<<NM, 256>>>(cur, go, gz);
        mma_gemm_nn<false><<<dim3(ND / 128, NM / 128), 256, SMEM_NN>>>(
            gz, Wq + (size_t)l * ND * ND, bq + (size_t)l * ND, gq, NM, ND, ND);
        mma_gemm_nn<false><<<dim3(ND / 128, NM / 128), 256, SMEM_NN>>>(
            gz, Wk + (size_t)l * ND * ND, bk + (size_t)l * ND, gk, NM, ND, ND);
        mma_gemm_nn<false><<<dim3(ND / 128, NM / 128), 256, SMEM_NN>>>(
            gz, Wv + (size_t)l * ND * ND, bv + (size_t)l * ND, gv, NM, ND, ND);
        mma_attn_scores<<<dim3(TT / 128, TT / 128, NB * NH), 256, SMEM_SC>>>(gk, gq, gs);
        softmax_kernel<<<NB * NH * TT, 256>>>(gs);
        mma_attn_out<<<dim3(TT / 128, NB * NH), 256, SMEM_AV>>>(gs, gv, go);
        float* dst = (l == NL - 1) ? out : gx;
        resnorm_kernel<<<NM, 256>>>(gz, go, dst);
        cur = gx;
    }
}

// round 10
// speedup vs baseline: 2.4442x; 1.1414x over previous
#include <cuda_runtime.h>
#include <cuda_bf16.h>
#include <math.h>
#include <stdint.h>

#define NL   4
#define TT   1024
#define NB   4
#define ND   1024
#define NH   16
#define HD   64
#define NFF  4096
#define NM   (TT*NB)
#define EPSN 1e-6f

typedef __nv_bfloat16 bf16;

// ---------------- fp32 scratch ----------------
__device__ float g_x[NM * ND];
__device__ float g_z[NM * ND];
__device__ float g_o[NM * ND];
__device__ float g_v[NM * ND];
__device__ float g_s[67108864];            // (64, TT, TT) fp32 scores, 256MB

// ---------------- bf16 hi/lo activations ----------------
__device__ bf16 g_xhi[NM * ND],  g_xlo[NM * ND];
__device__ bf16 g_zhi[NM * ND],  g_zlo[NM * ND];
__device__ bf16 g_hhi[NM * NFF], g_hlo[NM * NFF];
__device__ bf16 g_qhi[NM * ND],  g_qlo[NM * ND];
__device__ bf16 g_khi[NM * ND],  g_klo[NM * ND];
__device__ bf16 g_vthi[64 * HD * TT], g_vtlo[64 * HD * TT];   // [bh][d][t]
__device__ bf16 g_shi[67108864], g_slo[67108864];             // split probabilities

// ---------------- bf16 hi/lo transposed weights [N][K] ----------------
__device__ bf16 g_w1t_hi[NL * NFF * ND], g_w1t_lo[NL * NFF * ND];
__device__ bf16 g_w2t_hi[NL * ND * NFF], g_w2t_lo[NL * ND * NFF];
__device__ bf16 g_wqt_hi[NL * ND * ND],  g_wqt_lo[NL * ND * ND];
__device__ bf16 g_wkt_hi[NL * ND * ND],  g_wkt_lo[NL * ND * ND];
__device__ bf16 g_wvt_hi[NL * ND * ND],  g_wvt_lo[NL * ND * ND];

// ---------------- helpers ----------------
__device__ __forceinline__ void mma16(float* c, const uint32_t* a, const uint32_t* b) {
    asm volatile(
        "mma.sync.aligned.m16n8k16.row.col.f32.bf16.bf16.f32 "
        "{%0,%1,%2,%3}, {%4,%5,%6,%7}, {%8,%9}, {%0,%1,%2,%3};\n"
        : "+f"(c[0]), "+f"(c[1]), "+f"(c[2]), "+f"(c[3])
        : "r"(a[0]), "r"(a[1]), "r"(a[2]), "r"(a[3]), "r"(b[0]), "r"(b[1]));
}
__device__ __forceinline__ void bsplit(float x, float y, uint32_t& hi, uint32_t& lo) {
    uint32_t h;
    asm("cvt.rn.bf16x2.f32 %0, %1, %2;" : "=r"(h) : "f"(y), "f"(x));
    float xr = x - __uint_as_float(h << 16);
    float yr = y - __uint_as_float(h & 0xffff0000u);
    asm("cvt.rn.bf16x2.f32 %0, %1, %2;" : "=r"(lo) : "f"(yr), "f"(xr));
    hi = h;
}
__device__ __forceinline__ void cpa16(void* dst, const void* src) {
    uint32_t d = (uint32_t)__cvta_generic_to_shared(dst);
    asm volatile("cp.async.cg.shared.global [%0], [%1], 16;\n" :: "r"(d), "l"(src));
}
__device__ __forceinline__ void cp_commit() { asm volatile("cp.async.commit_group;\n"); }
template<int N> __device__ __forceinline__ void cp_wait() { asm volatile("cp.async.wait_group %0;\n" :: "n"(N)); }

// ======================= main GEMM: C = act(A@Bt' + bias) =======================
// A hi/lo [M][K] bf16 (k-contig), Bt hi/lo [N][K] bf16 (k-contig).
// 128x128x32 tile, 8 warps (2x4), 3-pass bf16 mma, double-buffered cp.async.
// smem rows padded to 40 bf16 (80B, 16B-aligned, conflict-free frag loads).
template<bool RELU, bool SPLIT>
__global__ __launch_bounds__(256, 2) void gemm_bf3(
    const bf16* __restrict__ Ahi, const bf16* __restrict__ Alo,
    const bf16* __restrict__ Bthi, const bf16* __restrict__ Btlo,
    const float* __restrict__ bias,
    float* __restrict__ C, bf16* __restrict__ Chi, bf16* __restrict__ Clo,
    int M, int N, int K)
{
    extern __shared__ __align__(16) uint8_t smraw[];
    bf16* As = (bf16*)smraw;               // [2 stage][2 half][128][40]
    bf16* Bs = As + 2 * 2 * 128 * 40;

    const int tid  = threadIdx.x;
    const int warp = tid >> 5, lane = tid & 31;
    const int g = lane >> 2, t = lane & 3;
    const int wm = warp >> 2, wn = warp & 3;
    const int m0 = blockIdx.y * 128, n0 = blockIdx.x * 128;
    const int nk = K >> 5;

    auto load_stage = [&](int s, int k0) {
        #pragma unroll
        for (int hf = 0; hf < 2; hf++) {
            const bf16* Asrc = hf ? Alo : Ahi;
            const bf16* Bsrc = hf ? Btlo : Bthi;
            bf16* Ad = As + (s * 2 + hf) * 128 * 40;
            bf16* Bd = Bs + (s * 2 + hf) * 128 * 40;
            #pragma unroll
            for (int q = 0; q < 2; q++) {
                int c = tid + 256 * q;
                int r = c >> 2, ch = (c & 3) * 8;
                cpa16(Ad + r * 40 + ch, Asrc + (size_t)(m0 + r) * K + k0 + ch);
                cpa16(Bd + r * 40 + ch, Bsrc + (size_t)(n0 + r) * K + k0 + ch);
            }
        }
    };

    float acc[4][4][4] = {};

    load_stage(0, 0);
    cp_commit();

    for (int kt = 0; kt < nk; kt++) {
        int s = kt & 1;
        if (kt + 1 < nk) {
            load_stage((kt + 1) & 1, (kt + 1) << 5);
            cp_commit();
            cp_wait<1>();
        } else {
            cp_wait<0>();
        }
        __syncthreads();

        const uint32_t* Ah = (const uint32_t*)(As + (s * 2 + 0) * 128 * 40) + wm * 64 * 20;
        const uint32_t* Al = (const uint32_t*)(As + (s * 2 + 1) * 128 * 40) + wm * 64 * 20;
        const uint32_t* Bh = (const uint32_t*)(Bs + (s * 2 + 0) * 128 * 40) + wn * 32 * 20;
        const uint32_t* Bl = (const uint32_t*)(Bs + (s * 2 + 1) * 128 * 40) + wn * 32 * 20;

        #pragma unroll
        for (int h2 = 0; h2 < 2; h2++) {
            const int kb = h2 * 8;
            uint32_t bhi[4][2], blo[4][2];
            #pragma unroll
            for (int j = 0; j < 4; j++) {
                int nb = (j * 8 + g) * 20 + t + kb;
                bhi[j][0] = Bh[nb]; bhi[j][1] = Bh[nb + 4];
                blo[j][0] = Bl[nb]; blo[j][1] = Bl[nb + 4];
            }
            #pragma unroll
            for (int i = 0; i < 4; i++) {
                int ra = (i * 16 + g) * 20 + t + kb, rb = ra + 8 * 20;
                uint32_t ahi[4] = { Ah[ra], Ah[rb], Ah[ra + 4], Ah[rb + 4] };
                uint32_t alo[4] = { Al[ra], Al[rb], Al[ra + 4], Al[rb + 4] };
                #pragma unroll
                for (int j = 0; j < 4; j++) {
                    mma16(acc[i][j], ahi, bhi[j]);
                    mma16(acc[i][j], ahi, blo[j]);
                    mma16(acc[i][j], alo, bhi[j]);
                }
            }
        }
        __syncthreads();
    }

    #pragma unroll
    for (int i = 0; i < 4; i++) {
        int row = m0 + wm * 64 + i * 16 + g;
        #pragma unroll
        for (int j = 0; j < 4; j++) {
            int col = n0 + wn * 32 + j * 8 + 2 * t;
            float b0 = bias[col], b1 = bias[col + 1];
            float v0 = acc[i][j][0] + b0, v1 = acc[i][j][1] + b1;
            float v2 = acc[i][j][2] + b0, v3 = acc[i][j][3] + b1;
            if (RELU) {
                v0 = fmaxf(v0, 0.f); v1 = fmaxf(v1, 0.f);
                v2 = fmaxf(v2, 0.f); v3 = fmaxf(v3, 0.f);
            }
            if (SPLIT) {
                uint32_t h0, l0, h1, l1;
                bsplit(v0, v1, h0, l0);
                bsplit(v2, v3, h1, l1);
                ((uint32_t*)Chi)[((size_t)row * N + col) >> 1]       = h0;
                ((uint32_t*)Clo)[((size_t)row * N + col) >> 1]       = l0;
                ((uint32_t*)Chi)[((size_t)(row + 8) * N + col) >> 1] = h1;
                ((uint32_t*)Clo)[((size_t)(row + 8) * N + col) >> 1] = l1;
            } else {
                *(float2*)(C + (size_t)row * N + col)       = make_float2(v0, v1);
                *(float2*)(C + (size_t)(row + 8) * N + col) = make_float2(v2, v3);
            }
        }
    }
}

// ======================= attention scores: S = K.Q^T / 32 (NT, K=64) =======================
// K/Q hi/lo [token-major][64] per (b,h); smem rows padded to 72 bf16 (144B).
__global__ __launch_bounds__(256, 2) void scores_bf3(
    const bf16* __restrict__ Khi, const bf16* __restrict__ Klo,
    const bf16* __restrict__ Qhi, const bf16* __restrict__ Qlo,
    float* __restrict__ S)
{
    extern __shared__ __align__(16) uint8_t smraw[];
    bf16* Ks = (bf16*)smraw;          // [2 half][128][72]
    bf16* Qs = Ks + 2 * 128 * 72;

    const int bh = blockIdx.z, b = bh >> 4, h = bh & 15;
    const int i0 = blockIdx.y * 128, j0 = blockIdx.x * 128;
    const int tid  = threadIdx.x;
    const int warp = tid >> 5, lane = tid & 31;
    const int g = lane >> 2, t = lane & 3;
    const int wm = warp >> 2, wn = warp & 3;

    const size_t base = (size_t)b * ND + (size_t)h * HD;
    #pragma unroll
    for (int hf = 0; hf < 2; hf++) {
        const bf16* Ksrc = hf ? Klo : Khi;
        const bf16* Qsrc = hf ? Qlo : Qhi;
        bf16* Kd = Ks + hf * 128 * 72;
        bf16* Qd = Qs + hf * 128 * 72;
        #pragma unroll
        for (int q = 0; q < 4; q++) {
            int c = tid + 256 * q;
            int r = c >> 3, ch = (c & 7) * 8;
            cpa16(Kd + r * 72 + ch, Ksrc + (size_t)(i0 + r) * (NB * ND) + base + ch);
            cpa16(Qd + r * 72 + ch, Qsrc + (size_t)(j0 + r) * (NB * ND) + base + ch);
        }
    }
    cp_commit();
    cp_wait<0>();
    __syncthreads();

    const uint32_t* Ah = (const uint32_t*)Ks + wm * 64 * 36;
    const uint32_t* Al = (const uint32_t*)(Ks + 128 * 72) + wm * 64 * 36;
    const uint32_t* Bh = (const uint32_t*)Qs + wn * 32 * 36;
    const uint32_t* Bl = (const uint32_t*)(Qs + 128 * 72) + wn * 32 * 36;

    float acc[4][4][4] = {};
    #pragma unroll
    for (int h2 = 0; h2 < 4; h2++) {
        const int kb = h2 * 8;
        uint32_t bhi[4][2], blo[4][2];
        #pragma unroll
        for (int j = 0; j < 4; j++) {
            int nb = (j * 8 + g) * 36 + t + kb;
            bhi[j][0] = Bh[nb]; bhi[j][1] = Bh[nb + 4];
            blo[j][0] = Bl[nb]; blo[j][1] = Bl[nb + 4];
        }
        #pragma unroll
        for (int i = 0; i < 4; i++) {
            int ra = (i * 16 + g) * 36 + t + kb, rb = ra + 8 * 36;
            uint32_t ahi[4] = { Ah[ra], Ah[rb], Ah[ra + 4], Ah[rb + 4] };
            uint32_t alo[4] = { Al[ra], Al[rb], Al[ra + 4], Al[rb + 4] };
            #pragma unroll
            for (int j = 0; j < 4; j++) {
                mma16(acc[i][j], ahi, bhi[j]);
                mma16(acc[i][j], ahi, blo[j]);
                mma16(acc[i][j], alo, bhi[j]);
            }
        }
    }

    float* Sp = S + (size_t)bh * TT * TT;
    #pragma unroll
    for (int i = 0; i < 4; i++) {
        int row = i0 + wm * 64 + i * 16 + g;
        #pragma unroll
        for (int j = 0; j < 4; j++) {
            int col = j0 + wn * 32 + j * 8 + 2 * t;
            *(float2*)(Sp + (size_t)row * TT + col) =
                make_float2(acc[i][j][0] * 0.03125f, acc[i][j][1] * 0.03125f);
            *(float2*)(Sp + (size_t)(row + 8) * TT + col) =
                make_float2(acc[i][j][2] * 0.03125f, acc[i][j][3] * 0.03125f);
        }
    }
}

// ======================= attention output: O = A @ V (A split, Vt split [bh][d][t]) =======================
__global__ __launch_bounds__(256, 2) void av_bf3(
    const bf16* __restrict__ Shi, const bf16* __restrict__ Slo,
    const bf16* __restrict__ Vthi, const bf16* __restrict__ Vtlo,
    float* __restrict__ O)
{
    extern __shared__ __align__(16) uint8_t smraw[];
    bf16* As = (bf16*)smraw;                // [2 stage][2 half][128][40]
    bf16* Bs = As + 2 * 2 * 128 * 40;       // [2 stage][2 half][64][40]

    const int bh = blockIdx.y, b = bh >> 4, h = bh & 15;
    const int i0 = blockIdx.x * 128;
    const int tid  = threadIdx.x;
    const int warp = tid >> 5, lane = tid & 31;
    const int g = lane >> 2, t = lane & 3;
    const int wm = warp >> 2, wn = warp & 3;

    const bf16* Sh = Shi + (size_t)bh * TT * TT + (size_t)i0 * TT;
    const bf16* Sl = Slo + (size_t)bh * TT * TT + (size_t)i0 * TT;
    const bf16* Vh = Vthi + (size_t)bh * HD * TT;
    const bf16* Vl = Vtlo + (size_t)bh * HD * TT;

    auto load_stage = [&](int s, int k0) {
        #pragma unroll
        for (int hf = 0; hf < 2; hf++) {
            const bf16* Asrc = hf ? Sl : Sh;
            const bf16* Bsrc = hf ? Vl : Vh;
            bf16* Ad = As + (s * 2 + hf) * 128 * 40;
            bf16* Bd = Bs + (s * 2 + hf) * 64 * 40;
            #pragma unroll
            for (int q = 0; q < 2; q++) {
                int c = tid + 256 * q;
                int r = c >> 2, ch = (c & 3) * 8;
                cpa16(Ad + r * 40 + ch, Asrc + (size_t)r * TT + k0 + ch);
            }
            {
                int r = tid >> 2, ch = (tid & 3) * 8;
                cpa16(Bd + r * 40 + ch, Bsrc + (size_t)r * TT + k0 + ch);
            }
        }
    };

    float acc[4][2][4] = {};

    load_stage(0, 0);
    cp_commit();

    const int nk = TT >> 5;
    for (int kt = 0; kt < nk; kt++) {
        int s = kt & 1;
        if (kt + 1 < nk) {
            load_stage((kt + 1) & 1, (kt + 1) << 5);
            cp_commit();
            cp_wait<1>();
        } else {
            cp_wait<0>();
        }
        __syncthreads();

        const uint32_t* Ah = (const uint32_t*)(As + (s * 2 + 0) * 128 * 40) + wm * 64 * 20;
        const uint32_t* Al = (const uint32_t*)(As + (s * 2 + 1) * 128 * 40) + wm * 64 * 20;
        const uint32_t* Bh = (const uint32_t*)(Bs + (s * 2 + 0) * 64 * 40) + wn * 16 * 20;
        const uint32_t* Bl = (const uint32_t*)(Bs + (s * 2 + 1) * 64 * 40) + wn * 16 * 20;

        #pragma unroll
        for (int h2 = 0; h2 < 2; h2++) {
            const int kb = h2 * 8;
            uint32_t bhi[2][2], blo[2][2];
            #pragma unroll
            for (int j = 0; j < 2; j++) {
                int nb = (j * 8 + g) * 20 + t + kb;
                bhi[j][0] = Bh[nb]; bhi[j][1] = Bh[nb + 4];
                blo[j][0] = Bl[nb]; blo[j][1] = Bl[nb + 4];
            }
            #pragma unroll
            for (int i = 0; i < 4; i++) {
                int ra = (i * 16 + g) * 20 + t + kb, rb = ra + 8 * 20;
                uint32_t ahi[4] = { Ah[ra], Ah[rb], Ah[ra + 4], Ah[rb + 4] };
                uint32_t alo[4] = { Al[ra], Al[rb], Al[ra + 4], Al[rb + 4] };
                #pragma unroll
                for (int j = 0; j < 2; j++) {
                    mma16(acc[i][j], ahi, bhi[j]);
                    mma16(acc[i][j], ahi, blo[j]);
                    mma16(acc[i][j], alo, bhi[j]);
                }
            }
        }
        __syncthreads();
    }

    #pragma unroll
    for (int i = 0; i < 4; i++) {
        int row = i0 + wm * 64 + i * 16 + g;
        #pragma unroll
        for (int j = 0; j < 2; j++) {
            int col = wn * 16 + j * 8 + 2 * t;
            *(float2*)(O + ((size_t)row * NB + b) * ND + h * HD + col) =
                make_float2(acc[i][j][0], acc[i][j][1]);
            *(float2*)(O + ((size_t)(row + 8) * NB + b) * ND + h * HD + col) =
                make_float2(acc[i][j][2], acc[i][j][3]);
        }
    }
}

// ---------------- weight transpose + split: W[K][N] -> Thi/Tlo [N][K] ----------------
__global__ __launch_bounds__(256) void transpose_split(
    const float* __restrict__ W, bf16* __restrict__ Thi, bf16* __restrict__ Tlo,
    int K, int N)
{
    __shared__ float tile[32][33];
    const int n0 = blockIdx.x * 32, k0 = blockIdx.y * 32;
    const int tx = threadIdx.x & 31, ty = threadIdx.x >> 5;
    #pragma unroll
    for (int p = 0; p < 4; p++)
        tile[ty + 8 * p][tx] = W[(size_t)(k0 + ty + 8 * p) * N + n0 + tx];
    __syncthreads();
    #pragma unroll
    for (int p = 0; p < 4; p++) {
        int n = n0 + ty + 8 * p, k = k0 + tx;
        float v = tile[tx][ty + 8 * p];
        bf16 hb = __float2bfloat16(v);
        Thi[(size_t)n * K + k] = hb;
        Tlo[(size_t)n * K + k] = __float2bfloat16(v - __bfloat162float(hb));
    }
}

// ---------------- V transpose + split: V fp32 [token-major][ND] -> Vt [bh][d][t] ----------------
__global__ __launch_bounds__(256) void vtrans_split(
    const float* __restrict__ V, bf16* __restrict__ Thi, bf16* __restrict__ Tlo)
{
    __shared__ float tile[32][33];
    const int bh = blockIdx.z, b = bh >> 4, h = bh & 15;
    const int t0 = blockIdx.x * 32, d0 = blockIdx.y * 32;
    const int tx = threadIdx.x & 31, ty = threadIdx.x >> 5;
    #pragma unroll
    for (int p = 0; p < 4; p++)
        tile[ty + 8 * p][tx] =
            V[((size_t)(t0 + ty + 8 * p) * NB + b) * ND + h * HD + d0 + tx];
    __syncthreads();
    #pragma unroll
    for (int p = 0; p < 4; p++) {
        int d = d0 + ty + 8 * p, tt = t0 + tx;
        float v = tile[tx][ty + 8 * p];
        bf16 hb = __float2bfloat16(v);
        size_t idx = ((size_t)bh * HD + d) * TT + tt;
        Thi[idx] = hb;
        Tlo[idx] = __float2bfloat16(v - __bfloat162float(hb));
    }
}

// ---------------- elementwise split (layer-0 input) ----------------
__global__ __launch_bounds__(256) void split_kernel(
    const float* __restrict__ X, bf16* __restrict__ hi, bf16* __restrict__ lo)
{
    size_t i = ((size_t)blockIdx.x * 256 + threadIdx.x) * 4;
    float4 v = *(const float4*)(X + i);
    uint32_t h0, l0, h1, l1;
    bsplit(v.x, v.y, h0, l0);
    bsplit(v.z, v.w, h1, l1);
    ((uint32_t*)hi)[i >> 1]       = h0;
    ((uint32_t*)lo)[i >> 1]       = l0;
    ((uint32_t*)hi)[(i >> 1) + 1] = h1;
    ((uint32_t*)lo)[(i >> 1) + 1] = l1;
}

// ---------------- resnorm (+optional split) ----------------
template<bool SPLIT>
__global__ __launch_bounds__(256) void resnorm_kernel(
    const float* __restrict__ x, const float* __restrict__ fx,
    float* __restrict__ out, bf16* __restrict__ ohi, bf16* __restrict__ olo)
{
    const int row = blockIdx.x;
    const int tid = threadIdx.x;
    const int lane = tid & 31, warp = tid >> 5;
    __shared__ float red0[8], red1[8], stat[2];

    float4 xv = *(const float4*)(x + (size_t)row * ND + tid * 4);
    float4 fv = *(const float4*)(fx + (size_t)row * ND + tid * 4);
    float4 y;
    y.x = xv.x + fv.x; y.y = xv.y + fv.y; y.z = xv.z + fv.z; y.w = xv.w + fv.w;

    float s  = y.x + y.y + y.z + y.w;
    float s2 = y.x * y.x + y.y * y.y + y.z * y.z + y.w * y.w;
    #pragma unroll
    for (int o = 16; o > 0; o >>= 1) {
        s  += __shfl_xor_sync(0xffffffffu, s, o);
        s2 += __shfl_xor_sync(0xffffffffu, s2, o);
    }
    if (lane == 0) { red0[warp] = s; red1[warp] = s2; }
    __syncthreads();
    if (tid == 0) {
        float a = 0.f, bb = 0.f;
        #pragma unroll
        for (int w = 0; w < 8; w++) { a += red0[w]; bb += red1[w]; }
        float mu  = a / (float)ND;
        float var = (bb - a * mu) / (float)(ND - 1);
        stat[0] = mu;
        stat[1] = 1.f / (sqrtf(fmaxf(var, 0.f)) + EPSN);
    }
    __syncthreads();
    const float mu = stat[0], inv = stat[1];
    float4 o;
    o.x = (y.x - mu) * inv; o.y = (y.y - mu) * inv;
    o.z = (y.z - mu) * inv; o.w = (y.w - mu) * inv;
    *(float4*)(out + (size_t)row * ND + tid * 4) = o;
    if (SPLIT) {
        uint32_t h0, l0, h1, l1;
        bsplit(o.x, o.y, h0, l0);
        bsplit(o.z, o.w, h1, l1);
        size_t base = ((size_t)row * ND + tid * 4) >> 1;
        ((uint32_t*)ohi)[base]     = h0;
        ((uint32_t*)olo)[base]     = l0;
        ((uint32_t*)ohi)[base + 1] = h1;
        ((uint32_t*)olo)[base + 1] = l1;
    }
}

// ---------------- row softmax (mask all-true), writes split bf16 ----------------
__global__ __launch_bounds__(256) void softmax_split_kernel(
    const float* __restrict__ S, bf16* __restrict__ Phi, bf16* __restrict__ Plo)
{
    const float* p = S + (size_t)blockIdx.x * TT;
    const int tid = threadIdx.x;
    const int lane = tid & 31, warp = tid >> 5;
    __shared__ float red[8], bc[1];

    float4 v = *(const float4*)(p + tid * 4);
    float m = fmaxf(fmaxf(v.x, v.y), fmaxf(v.z, v.w));
    #pragma unroll
    for (int o = 16; o > 0; o >>= 1) m = fmaxf(m, __shfl_xor_sync(0xffffffffu, m, o));
    if (lane == 0) red[warp] = m;
    __syncthreads();
    float bm = red[0];
    #pragma unroll
    for (int w = 1; w < 8; w++) bm = fmaxf(bm, red[w]);

    v.x = __expf(v.x - bm); v.y = __expf(v.y - bm);
    v.z = __expf(v.z - bm); v.w = __expf(v.w - bm);
    float s = v.x + v.y + v.z + v.w;
    #pragma unroll
    for (int o = 16; o > 0; o >>= 1) s += __shfl_xor_sync(0xffffffffu, s, o);
    __syncthreads();
    if (lane == 0) red[warp] = s;
    __syncthreads();
    if (tid == 0) {
        float a = 0.f;
        #pragma unroll
        for (int w = 0; w < 8; w++) a += red[w];
        bc[0] = 1.f / a;
    }
    __syncthreads();
    const float inv = bc[0];
    v.x *= inv; v.y *= inv; v.z *= inv; v.w *= inv;
    uint32_t h0, l0, h1, l1;
    bsplit(v.x, v.y, h0, l0);
    bsplit(v.z, v.w, h1, l1);
    size_t base = ((size_t)blockIdx.x * TT + tid * 4) >> 1;
    ((uint32_t*)Phi)[base]     = h0;
    ((uint32_t*)Plo)[base]     = l0;
    ((uint32_t*)Phi)[base + 1] = h1;
    ((uint32_t*)Plo)[base + 1] = l1;
}

// ---------------- host launcher ----------------
extern "C" void kernel_launch(void* const* d_in, const int* in_sizes, int n_in,
                              void* d_out, int out_size)
{
    const float* x_in = (const float*)d_in[0];
    const float* Wk = (const float*)d_in[2];
    const float* bk = (const float*)d_in[3];
    const float* Wq = (const float*)d_in[4];
    const float* bq = (const float*)d_in[5];
    const float* Wv = (const float*)d_in[6];
    const float* bv = (const float*)d_in[7];
    const float* W1 = (const float*)d_in[8];
    const float* b1 = (const float*)d_in[9];
    const float* W2 = (const float*)d_in[10];
    const float* b2 = (const float*)d_in[11];
    float* out = (float*)d_out;

    const int SMEM_NN = (2 * 2 * 128 * 40 * 2) * 2;          // 81920
    const int SMEM_SC = (2 * 128 * 72 * 2) * 2;              // 73728
    const int SMEM_AV = (2 * 2 * 128 * 40 + 2 * 2 * 64 * 40) * 2;  // 61440
    cudaFuncSetAttribute(gemm_bf3<true, true>,   cudaFuncAttributeMaxDynamicSharedMemorySize, SMEM_NN);
    cudaFuncSetAttribute(gemm_bf3<true, false>,  cudaFuncAttributeMaxDynamicSharedMemorySize, SMEM_NN);
    cudaFuncSetAttribute(gemm_bf3<false, true>,  cudaFuncAttributeMaxDynamicSharedMemorySize, SMEM_NN);
    cudaFuncSetAttribute(gemm_bf3<false, false>, cudaFuncAttributeMaxDynamicSharedMemorySize, SMEM_NN);
    cudaFuncSetAttribute(scores_bf3, cudaFuncAttributeMaxDynamicSharedMemorySize, SMEM_SC);
    cudaFuncSetAttribute(av_bf3,     cudaFuncAttributeMaxDynamicSharedMemorySize, SMEM_AV);

    // resolve device-global scratch
    void* p;
    #define SYM(v, sym) cudaGetSymbolAddress(&p, sym); auto* v = (decltype(&sym[0]))p;
    SYM(gx, g_x)   SYM(gz, g_z)   SYM(go, g_o)   SYM(gv, g_v)   SYM(gs, g_s)
    SYM(xhi, g_xhi) SYM(xlo, g_xlo) SYM(zhi, g_zhi) SYM(zlo, g_zlo)
    SYM(hhi, g_hhi) SYM(hlo, g_hlo) SYM(qhi, g_qhi) SYM(qlo, g_qlo)
    SYM(khi, g_khi) SYM(klo, g_klo) SYM(vthi, g_vthi) SYM(vtlo, g_vtlo)
    SYM(shi, g_shi) SYM(slo, g_slo)
    SYM(w1h, g_w1t_hi) SYM(w1l, g_w1t_lo) SYM(w2h, g_w2t_hi) SYM(w2l, g_w2t_lo)
    SYM(wqh, g_wqt_hi) SYM(wql, g_wqt_lo) SYM(wkh, g_wkt_hi) SYM(wkl, g_wkt_lo)
    SYM(wvh, g_wvt_hi) SYM(wvl, g_wvt_lo)
    #undef SYM

    // weight transpose+split (per replay; ~60us total)
    for (int l = 0; l < NL; l++) {
        transpose_split<<<dim3(NFF / 32, ND / 32), 256>>>(
            W1 + (size_t)l * ND * NFF, w1h + (size_t)l * NFF * ND, w1l + (size_t)l * NFF * ND, ND, NFF);
        transpose_split<<<dim3(ND / 32, NFF / 32), 256>>>(
            W2 + (size_t)l * NFF * ND, w2h + (size_t)l * ND * NFF, w2l + (size_t)l * ND * NFF, NFF, ND);
        transpose_split<<<dim3(ND / 32, ND / 32), 256>>>(
            Wq + (size_t)l * ND * ND, wqh + (size_t)l * ND * ND, wql + (size_t)l * ND * ND, ND, ND);
        transpose_split<<<dim3(ND / 32, ND / 32), 256>>>(
            Wk + (size_t)l * ND * ND, wkh + (size_t)l * ND * ND, wkl + (size_t)l * ND * ND, ND, ND);
        transpose_split<<<dim3(ND / 32, ND / 32), 256>>>(
            Wv + (size_t)l * ND * ND, wvh + (size_t)l * ND * ND, wvl + (size_t)l * ND * ND, ND, ND);
    }

    split_kernel<<<NM * ND / 1024, 256>>>(x_in, xhi, xlo);

    const float* cur = x_in;
    for (int l = 0; l < NL; l++) {
        // FF1: h = relu(x@W1+b1) -> split
        gemm_bf3<true, true><<<dim3(NFF / 128, NM / 128), 256, SMEM_NN>>>(
            xhi, xlo, w1h + (size_t)l * NFF * ND, w1l + (size_t)l * NFF * ND,
            b1 + (size_t)l * NFF, nullptr, hhi, hlo, NM, NFF, ND);
        // FF2: f = relu(h@W2+b2) -> fp32
        gemm_bf3<true, false><<<dim3(ND / 128, NM / 128), 256, SMEM_NN>>>(
            hhi, hlo, w2h + (size_t)l * ND * NFF, w2l + (size_t)l * ND * NFF,
            b2 + (size_t)l * ND, go, nullptr, nullptr, NM, ND, NFF);
        // z = resnorm(x, f) -> fp32 + split
        resnorm_kernel<true><<<NM, 256>>>(cur, go, gz, zhi, zlo);
        // Q, K -> split; V -> fp32
        gemm_bf3<false, true><<<dim3(ND / 128, NM / 128), 256, SMEM_NN>>>(
            zhi, zlo, wqh + (size_t)l * ND * ND, wql + (size_t)l * ND * ND,
            bq + (size_t)l * ND, nullptr, qhi, qlo, NM, ND, ND);
        gemm_bf3<false, true><<<dim3(ND / 128, NM / 128), 256, SMEM_NN>>>(
            zhi, zlo, wkh + (size_t)l * ND * ND, wkl + (size_t)l * ND * ND,
            bk + (size_t)l * ND, nullptr, khi, klo, NM, ND, ND);
        gemm_bf3<false, false><<<dim3(ND / 128, NM / 128), 256, SMEM_NN>>>(
            zhi, zlo, wvh + (size_t)l * ND * ND, wvl + (size_t)l * ND * ND,
            bv + (size_t)l * ND, gv, nullptr, nullptr, NM, ND, ND);
        vtrans_split<<<dim3(TT / 32, HD / 32, NB * NH), 256>>>(gv, vthi, vtlo);
        // attention
        scores_bf3<<<dim3(TT / 128, TT / 128, NB * NH), 256, SMEM_SC>>>(khi, klo, qhi, qlo, gs);
        softmax_split_kernel<<<NB * NH * TT, 256>>>(gs, shi, slo);
        av_bf3<<<dim3(TT / 128, NB * NH), 256, SMEM_AV>>>(shi, slo, vthi, vtlo, go);
        // x = resnorm(z, attn_out); split for next layer's FF1
        if (l == NL - 1) {
            resnorm_kernel<false><<<NM, 256>>>(gz, go, out, nullptr, nullptr);
        } else {
            resnorm_kernel<true><<<NM, 256>>>(gz, go, gx, xhi, xlo);
        }
        cur = gx;
    }
}